// round 7
// baseline (speedup 1.0000x reference)
#include <cuda_runtime.h>
#include <cuda_bf16.h>
#include <cstdint>

// LSTMNet: B=1024, T=2048, H=64, NC=10
// One CTA per batch element; 256 threads = 4 gates x 64 hidden units.
// Thread t: hid = t>>2, gate = t&3 (0=i,1=f,2=g,3=o), W row r = gate*64+hid.
// W_hh row kept in 32 packed u64 registers; h broadcast from smem (double-buffered);
// matvec via fma.rn.f32x2 (2 fp32 FMAs / instr). One __syncthreads per timestep.

#define T_LEN 2048
#define HDIM  64
#define NCLS  10

#define FMA2(acc, a, b) \
    asm("fma.rn.f32x2 %0, %1, %2, %0;" : "+l"(acc) : "l"(a), "l"(b))
#define ADD2(d, a, b) \
    asm("add.rn.f32x2 %0, %1, %2;" : "=l"(d) : "l"(a), "l"(b))

__device__ __forceinline__ float sigmoid_fast(float z) {
    // 1/(1+exp(-z)); __expf -> MUFU.EX2 path, ~2 ulp. Saturates correctly at +/-inf.
    float e = __expf(-z);
    return __fdividef(1.0f, 1.0f + e);
}

__global__ __launch_bounds__(256, 2)
void lstm_net_kernel(const float* __restrict__ x,
                     const float* __restrict__ W_ih,
                     const float* __restrict__ W_hh,
                     const float* __restrict__ b_ih,
                     const float* __restrict__ b_hh,
                     const float* __restrict__ fc1_w,
                     const float* __restrict__ fc1_b,
                     const float* __restrict__ fc2_w,
                     const float* __restrict__ fc2_b,
                     float* __restrict__ out)
{
    __shared__ __align__(16) float sx[T_LEN];      // this batch element's x row (8 KB)
    __shared__ __align__(16) float sh[2][HDIM];    // double-buffered hidden state
    __shared__ __align__(16) float sh1[HDIM];      // fc1 output

    const int b    = blockIdx.x;
    const int t    = threadIdx.x;
    const int hid  = t >> 2;
    const int gate = t & 3;
    const int r    = gate * HDIM + hid;            // row in the 4H-stacked params

    // ---- stage x[b, :] into smem (coalesced float4) ----
    {
        const float4* xr = reinterpret_cast<const float4*>(x + (size_t)b * T_LEN);
        float4* sx4 = reinterpret_cast<float4*>(sx);
        #pragma unroll
        for (int i = t; i < T_LEN / 4; i += 256) sx4[i] = xr[i];
    }

    // ---- W_hh row -> 32 packed (f32,f32) registers ----
    unsigned long long wp[32];
    {
        const ulonglong2* wrow = reinterpret_cast<const ulonglong2*>(W_hh + (size_t)r * HDIM);
        #pragma unroll
        for (int q = 0; q < 16; q++) {
            ulonglong2 v = wrow[q];
            wp[2 * q]     = v.x;
            wp[2 * q + 1] = v.y;
        }
    }
    const float w_in = W_ih[r];
    const float bias = b_ih[r] + b_hh[r];

    // activation selection, branchless: gate 2 -> tanh(z) = 2*sigmoid(2z)-1
    const float zscale = (gate == 2) ? 2.0f : 1.0f;
    const float alpha  = (gate == 2) ? 2.0f : 1.0f;
    const float beta   = (gate == 2) ? -1.0f : 0.0f;

    if (t < HDIM) sh[0][t] = 0.0f;
    float c = 0.0f;
    __syncthreads();

    #pragma unroll 1
    for (int step = 0; step < T_LEN; step++) {
        const int p = step & 1;
        const float xt  = sx[step];
        const float pre = fmaf(xt, w_in, bias);

        unsigned long long acc0 = (unsigned long long)__float_as_uint(pre); // (pre, 0.0f)
        unsigned long long acc1 = 0ull, acc2 = 0ull, acc3 = 0ull;

        const ulonglong2* hp = reinterpret_cast<const ulonglong2*>(sh[p]);
        #pragma unroll
        for (int q = 0; q < 16; q++) {
            ulonglong2 hv = hp[q];               // LDS.128 broadcast
            if (q & 1) {
                FMA2(acc2, wp[2 * q],     hv.x);
                FMA2(acc3, wp[2 * q + 1], hv.y);
            } else {
                FMA2(acc0, wp[2 * q],     hv.x);
                FMA2(acc1, wp[2 * q + 1], hv.y);
            }
        }
        unsigned long long s01, s23, s;
        ADD2(s01, acc0, acc1);
        ADD2(s23, acc2, acc3);
        ADD2(s,   s01,  s23);
        float gsum = __uint_as_float((unsigned)s) + __uint_as_float((unsigned)(s >> 32));

        // branchless activation
        float sg  = sigmoid_fast(gsum * zscale);
        float act = fmaf(sg, alpha, beta);

        // gather the quad's 4 activated gates (i,f,g,o) — all lanes get their quad
        float iv = __shfl_sync(0xffffffffu, act, 0, 4);
        float fv = __shfl_sync(0xffffffffu, act, 1, 4);
        float gv = __shfl_sync(0xffffffffu, act, 2, 4);
        float ov = __shfl_sync(0xffffffffu, act, 3, 4);

        // all 4 lanes of a quad compute identical c (replicated, consistent)
        c = fmaf(fv, c, iv * gv);
        float e2 = __expf(-2.0f * c);
        float th = __fdividef(2.0f, 1.0f + e2) - 1.0f;   // tanh(c)
        float hnew = ov * th;

        if (gate == 0) sh[1 - p][hid] = hnew;
        __syncthreads();
    }

    // final h is in sh[0] (T_LEN even: last write went to buffer 1-((T-1)&1) = 0)
    const float* hf = sh[T_LEN & 1];

    // ---- fc1 + relu (64 threads) ----
    if (t < HDIM) {
        float a = fc1_b[t];
        const float* wr = fc1_w + t * HDIM;
        #pragma unroll 16
        for (int k = 0; k < HDIM; k++) a = fmaf(wr[k], hf[k], a);
        sh1[t] = fmaxf(a, 0.0f);
    }
    __syncthreads();

    // ---- fc2 (10 threads) ----
    if (t < NCLS) {
        float a = fc2_b[t];
        const float* wr = fc2_w + t * HDIM;
        #pragma unroll 16
        for (int k = 0; k < HDIM; k++) a = fmaf(wr[k], sh1[k], a);
        out[(size_t)b * NCLS + t] = a;
    }
}

extern "C" void kernel_launch(void* const* d_in, const int* in_sizes, int n_in,
                              void* d_out, int out_size)
{
    const float* x     = (const float*)d_in[0];
    const float* W_ih  = (const float*)d_in[1];
    const float* W_hh  = (const float*)d_in[2];
    const float* b_ih  = (const float*)d_in[3];
    const float* b_hh  = (const float*)d_in[4];
    const float* fc1_w = (const float*)d_in[5];
    const float* fc1_b = (const float*)d_in[6];
    const float* fc2_w = (const float*)d_in[7];
    const float* fc2_b = (const float*)d_in[8];
    float* out = (float*)d_out;

    const int B = in_sizes[0] / T_LEN;   // 1024

    lstm_net_kernel<<<B, 256>>>(x, W_ih, W_hh, b_ih, b_hh,
                                fc1_w, fc1_b, fc2_w, fc2_b, out);
}